// round 16
// baseline (speedup 1.0000x reference)
#include <cuda_runtime.h>
#include <cuda_fp16.h>
#include <cstdint>
#include <math.h>

// ---------------- problem constants ----------------
#define BB       8
#define NN_      1024
#define MM_      1024
#define IND      12544
#define APP_MDIM 1024
#define APP_DIM  256
#define HEADS    4
#define MD       256
#define DVV      64

typedef __half h16;

// ---------------- scratch (device globals) ----------------
__device__ h16 g_A1h[(size_t)BB * NN_ * IND];
__device__ h16 g_A2h[(size_t)BB * MM_ * IND];
__device__ h16 g_Wkh[(size_t)APP_MDIM * IND];
__device__ h16 g_Wqh[(size_t)APP_MDIM * IND];
__device__ h16 g_Wvh[(size_t)APP_DIM * IND];
__device__ h16 g_Kh[(size_t)BB * NN_ * APP_MDIM];
__device__ h16 g_Qh[(size_t)BB * MM_ * APP_MDIM];
__device__ h16 g_Vth[(size_t)BB * HEADS * DVV * NN_];   // [b,h][dv][n]

// ============================================================================
// helpers
// ============================================================================
__device__ __forceinline__ uint32_t smem_u32(const void* p) {
    uint32_t a;
    asm("{ .reg .u64 t; cvta.to.shared.u64 t, %1; cvt.u32.u64 %0, t; }" : "=r"(a) : "l"(p));
    return a;
}
__device__ __forceinline__ uint32_t pack2h(h16 a, h16 b) {
    return ((uint32_t)__half_as_ushort(b) << 16) | (uint32_t)__half_as_ushort(a);
}
__device__ __forceinline__ uint32_t sw128(uint32_t off) {
    return off ^ ((off >> 3) & 0x70);
}
__device__ __forceinline__ void ldsm4(uint32_t* r, uint32_t addr) {
    asm volatile("ldmatrix.sync.aligned.m8n8.x4.shared.b16 {%0,%1,%2,%3}, [%4];"
                 : "=r"(r[0]), "=r"(r[1]), "=r"(r[2]), "=r"(r[3]) : "r"(addr));
}
__device__ __forceinline__ void mma16(float* d, const uint32_t* a, const uint32_t* b) {
    asm volatile(
        "mma.sync.aligned.m16n8k16.row.col.f32.f16.f16.f32 "
        "{%0,%1,%2,%3},{%4,%5,%6,%7},{%8,%9},{%0,%1,%2,%3};"
        : "+f"(d[0]), "+f"(d[1]), "+f"(d[2]), "+f"(d[3])
        : "r"(a[0]), "r"(a[1]), "r"(a[2]), "r"(a[3]), "r"(b[0]), "r"(b[1]));
}
#define CP16(dst, src) \
    asm volatile("cp.async.cg.shared.global [%0], [%1], 16;" :: "r"(dst), "l"(src))
#define CP_COMMIT() asm volatile("cp.async.commit_group;" ::: "memory")

// cubic Taylor exp: valid for |x| <= ~0.25 (here |x| <= ~0.06)
__device__ __forceinline__ float exp_poly(float x) {
    return 1.0f + x * (1.0f + x * (0.5f + x * (1.0f / 6.0f)));
}

// ============================================================================
// Unified projection kernel: K, Q, V — fp16 single-pass.
// BM=128, BN=256, 512 threads (2x8 warps, 64x32 warp tiles).
// 4-slot ring (BK=64), wait_group(2); next load issued BEFORE compute so the
// cp.async issue burst overlaps MMA and 3 chunks stay in flight.
// grid = (9, 64): x<4 K-cols, x<8 Q-cols, x==8 V.
// ============================================================================
#define PCHUNK (128 * 128 + 256 * 128)     // 49152: A(16K)+B(32K)
#define SM_PROJ (4 * PCHUNK)               // 196608

__global__ void __launch_bounds__(512, 1) proj_all_kernel(
    const float* __restrict__ bk, const float* __restrict__ bq,
    const float* __restrict__ bv)
{
    extern __shared__ char sm[];
    const uint32_t sbase = smem_u32(sm);
    const int tid = threadIdx.x;
    const int wid = tid >> 5, lane = tid & 31;
    const int warp_m = wid >> 3, warp_n = wid & 7;

    const int x = blockIdx.x;
    const h16 *A, *W;
    const float* bias;
    int task, colBase;
    if (x < 4)      { A = g_A1h; W = g_Wkh; bias = bk; task = 0; colBase = x * 256; }
    else if (x < 8) { A = g_A2h; W = g_Wqh; bias = bq; task = 1; colBase = (x - 4) * 256; }
    else            { A = g_A1h; W = g_Wvh; bias = bv; task = 2; colBase = 0; }
    const int rowBase = blockIdx.y * 128;

    float acc[4][4][4];
#pragma unroll
    for (int i = 0; i < 4; i++)
#pragma unroll
        for (int j = 0; j < 4; j++)
#pragma unroll
            for (int k = 0; k < 4; k++) acc[i][j][k] = 0.f;

    auto load_chunk = [&](int chunk) {
        const uint32_t base = sbase + (chunk & 3) * PCHUNK;
        const int k0 = chunk * 64;
#pragma unroll
        for (int i = tid; i < 128 * 8; i += 512) {
            int r = i >> 3, c = i & 7;
            CP16(base + sw128((uint32_t)i * 16),
                 A + (size_t)(rowBase + r) * IND + k0 + c * 8);
        }
#pragma unroll
        for (int i = tid; i < 256 * 8; i += 512) {
            int r = i >> 3, c = i & 7;
            CP16(base + 16384 + sw128((uint32_t)i * 16),
                 W + (size_t)(colBase + r) * IND + k0 + c * 8);
        }
        CP_COMMIT();
    };
    auto compute = [&](uint32_t sA) {
        const uint32_t sB = sA + 16384;
#pragma unroll
        for (int k16 = 0; k16 < 4; k16++) {
            const int aRow = warp_m * 64 + (lane & 15);
            const int aChunk = k16 * 2 + (lane >> 4);
            const int bRow = warp_n * 32 + (lane & 7) + ((lane >> 4) << 3);
            const int bChunk = k16 * 2 + ((lane >> 3) & 1);
            uint32_t af[4][4];
#pragma unroll
            for (int mf = 0; mf < 4; mf++)
                ldsm4(af[mf], sA + sw128((uint32_t)((aRow + mf * 16) * 128 + aChunk * 16)));
            uint32_t bfr[2][4];
            ldsm4(bfr[0], sB + sw128((uint32_t)(bRow * 128 + bChunk * 16)));
            ldsm4(bfr[1], sB + sw128((uint32_t)((bRow + 16) * 128 + bChunk * 16)));
#pragma unroll
            for (int mf = 0; mf < 4; mf++)
#pragma unroll
                for (int nf = 0; nf < 2; nf++) {
                    mma16(acc[mf][nf * 2 + 0], af[mf], &bfr[nf][0]);
                    mma16(acc[mf][nf * 2 + 1], af[mf], &bfr[nf][2]);
                }
        }
    };

    const int nch = IND / 64;    // 196
    load_chunk(0);
    load_chunk(1);
    load_chunk(2);

#pragma unroll 1
    for (int c = 0; c < nch; ++c) {
        asm volatile("cp.async.wait_group 2;" ::: "memory");
        __syncthreads();
        // issue next load BEFORE compute: slot (c+3)&3 == (c-1)&3, whose last
        // reader finished at the sync above; accounting stays 1 commit/iter.
        if (c + 3 < nch) load_chunk(c + 3);
        else CP_COMMIT();
        compute(sbase + (c & 3) * PCHUNK);
    }

    // ---- epilogue ----
#pragma unroll
    for (int mf = 0; mf < 4; mf++) {
#pragma unroll
        for (int nf = 0; nf < 4; nf++) {
            const int r0 = rowBase + warp_m * 64 + mf * 16 + (lane >> 2);
            const int c0 = colBase + warp_n * 32 + nf * 8 + (lane & 3) * 2;
#pragma unroll
            for (int half = 0; half < 2; half++) {
                const int rr = r0 + half * 8;
                const float v0 = acc[mf][nf][half * 2 + 0] + bias[c0];
                const float v1 = acc[mf][nf][half * 2 + 1] + bias[c0 + 1];
                if (task == 0) {
                    h16* p = g_Kh + (size_t)rr * APP_MDIM + c0;
                    p[0] = __float2half_rn(v0);
                    p[1] = __float2half_rn(v1);
                } else if (task == 1) {
                    h16* p = g_Qh + (size_t)rr * APP_MDIM + c0;
                    p[0] = __float2half_rn(v0);
                    p[1] = __float2half_rn(v1);
                } else {
#pragma unroll
                    for (int e = 0; e < 2; e++) {
                        const int cc = c0 + e;
                        const int b = rr >> 10, n = rr & 1023;
                        const int hh = cc >> 6, v = cc & 63;
                        g_Vth[(((size_t)(b * HEADS + hh)) * DVV + v) * NN_ + n] =
                            __float2half_rn(e ? v1 : v0);
                    }
                }
            }
        }
    }
}

// ============================================================================
// Fused attention (fp16): Q fragments in registers, poly-exp softmax, 1-pass PV.
// ============================================================================
#define ATT_NC      64
#define ATT_CHUNKS  (NN_ / ATT_NC)      // 16
#define ATT_QBYTES  65536
#define ATT_KBYTES  32768
#define ATT_STAGE   40960               // K + V
#define ATT_SNORM   (ATT_QBYTES + 4 * ATT_STAGE)   // 229376
#define ATT_SMEM    (ATT_SNORM + 512)              // 229888

__global__ void __launch_bounds__(256, 1) attn_fused_kernel(float* __restrict__ out)
{
    extern __shared__ char sm[];
    const uint32_t sbase = smem_u32(sm);
    const int tid = threadIdx.x, wid = tid >> 5, lane = tid & 31;
    const int z = blockIdx.y, b = z >> 2, h = z & 3;
    const int mbase = blockIdx.x * 128;

    const h16* Qg = g_Qh + ((size_t)(b * 1024 + mbase)) * 1024 + h * 256;
    const h16* Kg = g_Kh + ((size_t)(b * 1024)) * 1024 + h * 256;
    const h16* Vhg = g_Vth + (size_t)z * DVV * NN_;

#pragma unroll
    for (int j = 0; j < 16; j++) {
        int i = tid + j * 256;
        int ks = i >> 10, r = (i >> 3) & 127, c = i & 7;
        CP16(sbase + ks * 16384 + sw128((uint32_t)(r * 128 + c * 16)),
             Qg + (size_t)r * 1024 + ks * 64 + c * 8);
    }
    CP_COMMIT();

    auto load_kv = [&](int it) {
        const uint32_t st = sbase + ATT_QBYTES + (it & 3) * ATT_STAGE;
        const int n0 = it * ATT_NC;
#pragma unroll
        for (int j = 0; j < 8; j++) {
            int i = tid + j * 256;
            int ks = i >> 9, r = (i >> 3) & 63, c = i & 7;
            CP16(st + ks * 8192 + sw128((uint32_t)(r * 128 + c * 16)),
                 Kg + (size_t)(n0 + r) * 1024 + ks * 64 + c * 8);
        }
#pragma unroll
        for (int j = 0; j < 2; j++) {
            int i = tid + j * 256;
            int r = i >> 3, c = i & 7;
            CP16(st + ATT_KBYTES + sw128((uint32_t)(r * 128 + c * 16)),
                 Vhg + (size_t)r * NN_ + n0 + c * 8);
        }
        CP_COMMIT();
    };
    load_kv(0);
    load_kv(1);
    load_kv(2);

    asm volatile("cp.async.wait_group 3;" ::: "memory");   // Q landed
    __syncthreads();

    if (tid < 128) {
        float ss = 0.f;
#pragma unroll
        for (int ks = 0; ks < 4; ks++)
#pragma unroll
            for (int c = 0; c < 8; c++) {
                uint4 v = *(uint4*)(sm + ks * 16384 + sw128((uint32_t)(tid * 128 + c * 16)));
                uint32_t ww[4] = {v.x, v.y, v.z, v.w};
#pragma unroll
                for (int e = 0; e < 4; e++) {
                    float lo = __half2float(__ushort_as_half((uint16_t)(ww[e] & 0xffff)));
                    float hi = __half2float(__ushort_as_half((uint16_t)(ww[e] >> 16)));
                    ss += lo * lo + hi * hi;
                }
            }
        *(float*)(sm + ATT_SNORM + tid * 4) = rsqrtf(ss) * (1.0f / 256.0f);
    }
    __syncthreads();

    const int rw = wid * 16 + (lane >> 2);
    const float sc0 = *(const float*)(sm + ATT_SNORM + rw * 4);
    const float sc1 = *(const float*)(sm + ATT_SNORM + (rw + 8) * 4);

    const int aRow = wid * 16 + (lane & 15);
    const int bRowBase = (lane & 7) + ((lane >> 4) << 3);
    uint32_t qf[4][4][4];
#pragma unroll
    for (int ks = 0; ks < 4; ks++)
#pragma unroll
        for (int k16 = 0; k16 < 4; k16++) {
            const int aChunk = k16 * 2 + (lane >> 4);
            ldsm4(qf[ks][k16],
                  sbase + ks * 16384 + sw128((uint32_t)(aRow * 128 + aChunk * 16)));
        }

    float acc_o[8][4];
#pragma unroll
    for (int j = 0; j < 8; j++)
#pragma unroll
        for (int e = 0; e < 4; e++) acc_o[j][e] = 0.f;
    float ps0a = 0.f, ps0b = 0.f, ps1a = 0.f, ps1b = 0.f;

#pragma unroll 1
    for (int it = 0; it < ATT_CHUNKS; ++it) {
        asm volatile("cp.async.wait_group 2;" ::: "memory");
        __syncthreads();
        const uint32_t st = sbase + ATT_QBYTES + (it & 3) * ATT_STAGE;

        float acc_s[8][4];
#pragma unroll
        for (int t = 0; t < 8; t++)
#pragma unroll
            for (int e = 0; e < 4; e++) acc_s[t][e] = 0.f;

#pragma unroll
        for (int ks = 0; ks < 4; ks++) {
#pragma unroll
            for (int k16 = 0; k16 < 4; k16++) {
                const int bChunk = k16 * 2 + ((lane >> 3) & 1);
#pragma unroll
                for (int p = 0; p < 4; p++) {
                    uint32_t bfr[4];
                    ldsm4(bfr, st + ks * 8192 +
                               sw128((uint32_t)((p * 16 + bRowBase) * 128 + bChunk * 16)));
                    mma16(acc_s[p * 2 + 0], qf[ks][k16], &bfr[0]);
                    mma16(acc_s[p * 2 + 1], qf[ks][k16], &bfr[2]);
                }
            }
        }

        uint32_t pph[8][2];
#pragma unroll
        for (int t = 0; t < 8; t++) {
            float p0 = exp_poly(acc_s[t][0] * sc0);
            float p1 = exp_poly(acc_s[t][1] * sc0);
            float p2 = exp_poly(acc_s[t][2] * sc1);
            float p3 = exp_poly(acc_s[t][3] * sc1);
            if (t & 1) { ps0b += p0 + p1; ps1b += p2 + p3; }
            else       { ps0a += p0 + p1; ps1a += p2 + p3; }
            pph[t][0] = pack2h(__float2half_rn(p0), __float2half_rn(p1));
            pph[t][1] = pack2h(__float2half_rn(p2), __float2half_rn(p3));
        }

        const uint32_t vh = st + ATT_KBYTES;
#pragma unroll
        for (int kk = 0; kk < 4; kk++) {
            uint32_t Ahf[4] = {pph[2 * kk][0], pph[2 * kk][1],
                               pph[2 * kk + 1][0], pph[2 * kk + 1][1]};
            const int bChunk = kk * 2 + ((lane >> 3) & 1);
#pragma unroll
            for (int p = 0; p < 4; p++) {
                uint32_t bh[4];
                ldsm4(bh, vh + sw128((uint32_t)((p * 16 + bRowBase) * 128 + bChunk * 16)));
                mma16(acc_o[p * 2 + 0], Ahf, &bh[0]);
                mma16(acc_o[p * 2 + 1], Ahf, &bh[2]);
            }
        }

        if (it + 3 < ATT_CHUNKS) load_kv(it + 3);
        else CP_COMMIT();
    }

    float psum0 = ps0a + ps0b, psum1 = ps1a + ps1b;
    psum0 += __shfl_xor_sync(0xffffffffu, psum0, 1);
    psum0 += __shfl_xor_sync(0xffffffffu, psum0, 2);
    psum1 += __shfl_xor_sync(0xffffffffu, psum1, 1);
    psum1 += __shfl_xor_sync(0xffffffffu, psum1, 2);
    const float inv0 = 1.0f / psum0, inv1 = 1.0f / psum1;

    const int m0 = mbase + rw;
#pragma unroll
    for (int j = 0; j < 8; j++) {
        const int col = h * 64 + j * 8 + (lane & 3) * 2;
        float2 o0 = make_float2(acc_o[j][0] * inv0, acc_o[j][1] * inv0);
        float2 o1 = make_float2(acc_o[j][2] * inv1, acc_o[j][3] * inv1);
        *(float2*)(out + ((size_t)(b * 1024 + m0)) * 256 + col) = o0;
        *(float2*)(out + ((size_t)(b * 1024 + m0 + 8)) * 256 + col) = o1;
    }
}

// ============================================================================
// prep kernels
// ============================================================================
// wide convert: 2x float4 in -> 1x uint4 out per thread, both tensors
__global__ void __launch_bounds__(512) convert_kernel(
    const float4* __restrict__ A1, const float4* __restrict__ A2, int n8)
{
    int i = blockIdx.x * blockDim.x + threadIdx.x;
    const float4* src;
    uint4* dst;
    int j;
    if (i < n8) { src = A1; dst = reinterpret_cast<uint4*>(g_A1h); j = i; }
    else {
        j = i - n8;
        if (j >= n8) return;
        src = A2; dst = reinterpret_cast<uint4*>(g_A2h);
    }
    float4 a = src[2 * j], b = src[2 * j + 1];
    dst[j] = make_uint4(
        pack2h(__float2half_rn(a.x), __float2half_rn(a.y)),
        pack2h(__float2half_rn(a.z), __float2half_rn(a.w)),
        pack2h(__float2half_rn(b.x), __float2half_rn(b.y)),
        pack2h(__float2half_rn(b.z), __float2half_rn(b.w)));
}

__global__ void __launch_bounds__(256) wsplit3_kernel(
    const float* __restrict__ Wk, const float* __restrict__ Wq,
    const float* __restrict__ Wv)
{
    const float* W;
    h16* Th;
    int Nc;
    if (blockIdx.z == 0)      { W = Wk; Th = g_Wkh; Nc = APP_MDIM; }
    else if (blockIdx.z == 1) { W = Wq; Th = g_Wqh; Nc = APP_MDIM; }
    else                      { W = Wv; Th = g_Wvh; Nc = APP_DIM; }
    if ((int)blockIdx.x * 32 >= Nc) return;

    __shared__ float ts[32][33];
    int k0 = blockIdx.y * 32, n0 = blockIdx.x * 32;
    int tx = threadIdx.x & 31, ty = threadIdx.x >> 5;
#pragma unroll
    for (int i = 0; i < 4; i++)
        ts[ty + i * 8][tx] = W[(size_t)(k0 + ty + i * 8) * Nc + n0 + tx];
    __syncthreads();
#pragma unroll
    for (int i = 0; i < 4; i++) {
        int n = n0 + ty + i * 8, k = k0 + tx;
        Th[(size_t)n * IND + k] = __float2half_rn(ts[tx][ty + i * 8]);
    }
}

// ============================================================================
// Launch — simple serial (proven fastest structure)
// ============================================================================
extern "C" void kernel_launch(void* const* d_in, const int* in_sizes, int n_in,
                              void* d_out, int out_size)
{
    const float* first_app  = (const float*)d_in[0];
    const float* second_app = (const float*)d_in[1];
    const float* Wk = (const float*)d_in[2];
    const float* bk = (const float*)d_in[3];
    const float* Wq = (const float*)d_in[4];
    const float* bq = (const float*)d_in[5];
    const float* Wv = (const float*)d_in[6];
    const float* bv = (const float*)d_in[7];
    float* out = (float*)d_out;

    cudaFuncSetAttribute(proj_all_kernel, cudaFuncAttributeMaxDynamicSharedMemorySize, SM_PROJ);
    cudaFuncSetAttribute(attn_fused_kernel, cudaFuncAttributeMaxDynamicSharedMemorySize, ATT_SMEM);

    // 1) convert activations to fp16 (both tensors, one launch)
    {
        int n8 = (BB * NN_ * IND) / 8;
        convert_kernel<<<(2 * n8 + 511) / 512, 512>>>(
            (const float4*)first_app, (const float4*)second_app, n8);
    }
    // 2) weight transpose to fp16
    wsplit3_kernel<<<dim3(APP_MDIM / 32, IND / 32, 3), 256>>>(Wk, Wq, Wv);

    // 3) all projections: K (x=0..3), Q (x=4..7), V (x=8)
    proj_all_kernel<<<dim3(9, (BB * NN_) / 128), 512, SM_PROJ>>>(bk, bq, bv);

    // 4) fused attention
    attn_fused_kernel<<<dim3(MM_ / 128, BB * HEADS), 256, ATT_SMEM>>>(out);
}

// round 17
// speedup vs baseline: 1.0554x; 1.0554x over previous
#include <cuda_runtime.h>
#include <cuda_fp16.h>
#include <cstdint>
#include <math.h>

// ---------------- problem constants ----------------
#define BB       8
#define NN_      1024
#define MM_      1024
#define IND      12544
#define APP_MDIM 1024
#define APP_DIM  256
#define HEADS    4
#define MD       256
#define DVV      64

typedef __half h16;

// ---------------- scratch (device globals) ----------------
__device__ h16 g_A1h[(size_t)BB * NN_ * IND];
__device__ h16 g_A2h[(size_t)BB * MM_ * IND];
__device__ h16 g_Wkh[(size_t)APP_MDIM * IND];
__device__ h16 g_Wqh[(size_t)APP_MDIM * IND];
__device__ h16 g_Wvh[(size_t)APP_DIM * IND];
__device__ h16 g_Kh[(size_t)BB * NN_ * APP_MDIM];
__device__ h16 g_Qh[(size_t)BB * MM_ * APP_MDIM];
__device__ h16 g_Vth[(size_t)BB * HEADS * DVV * NN_];   // [b,h][dv][n]

// ============================================================================
// helpers
// ============================================================================
__device__ __forceinline__ uint32_t smem_u32(const void* p) {
    uint32_t a;
    asm("{ .reg .u64 t; cvta.to.shared.u64 t, %1; cvt.u32.u64 %0, t; }" : "=r"(a) : "l"(p));
    return a;
}
__device__ __forceinline__ uint32_t pack2h(h16 a, h16 b) {
    return ((uint32_t)__half_as_ushort(b) << 16) | (uint32_t)__half_as_ushort(a);
}
__device__ __forceinline__ uint32_t sw128(uint32_t off) {
    return off ^ ((off >> 3) & 0x70);
}
__device__ __forceinline__ void ldsm4(uint32_t* r, uint32_t addr) {
    asm volatile("ldmatrix.sync.aligned.m8n8.x4.shared.b16 {%0,%1,%2,%3}, [%4];"
                 : "=r"(r[0]), "=r"(r[1]), "=r"(r[2]), "=r"(r[3]) : "r"(addr));
}
__device__ __forceinline__ void mma16(float* d, const uint32_t* a, const uint32_t* b) {
    asm volatile(
        "mma.sync.aligned.m16n8k16.row.col.f32.f16.f16.f32 "
        "{%0,%1,%2,%3},{%4,%5,%6,%7},{%8,%9},{%0,%1,%2,%3};"
        : "+f"(d[0]), "+f"(d[1]), "+f"(d[2]), "+f"(d[3])
        : "r"(a[0]), "r"(a[1]), "r"(a[2]), "r"(a[3]), "r"(b[0]), "r"(b[1]));
}
#define CP16(dst, src) \
    asm volatile("cp.async.cg.shared.global [%0], [%1], 16;" :: "r"(dst), "l"(src))
#define CP_COMMIT() asm volatile("cp.async.commit_group;" ::: "memory")

// cubic Taylor exp: valid for |x| <= ~0.25 (here |x| <= ~0.06)
__device__ __forceinline__ float exp_poly(float x) {
    return 1.0f + x * (1.0f + x * (0.5f + x * (1.0f / 6.0f)));
}

// ============================================================================
// Unified projection kernel: K, Q, V — fp16 single-pass.
// BM=128, BN=256, 512 threads (2x8 warps, 64x32 warp tiles).
// 4-slot ring (BK=64), wait_group(2), R13-proven order: compute THEN load.
// grid = (9, 64): x<4 K-cols, x<8 Q-cols, x==8 V.
// ============================================================================
#define PCHUNK (128 * 128 + 256 * 128)     // 49152: A(16K)+B(32K)
#define SM_PROJ (4 * PCHUNK)               // 196608

__global__ void __launch_bounds__(512, 1) proj_all_kernel(
    const float* __restrict__ bk, const float* __restrict__ bq,
    const float* __restrict__ bv)
{
    extern __shared__ char sm[];
    const uint32_t sbase = smem_u32(sm);
    const int tid = threadIdx.x;
    const int wid = tid >> 5, lane = tid & 31;
    const int warp_m = wid >> 3, warp_n = wid & 7;

    const int x = blockIdx.x;
    const h16 *A, *W;
    const float* bias;
    int task, colBase;
    if (x < 4)      { A = g_A1h; W = g_Wkh; bias = bk; task = 0; colBase = x * 256; }
    else if (x < 8) { A = g_A2h; W = g_Wqh; bias = bq; task = 1; colBase = (x - 4) * 256; }
    else            { A = g_A1h; W = g_Wvh; bias = bv; task = 2; colBase = 0; }
    const int rowBase = blockIdx.y * 128;

    float acc[4][4][4];
#pragma unroll
    for (int i = 0; i < 4; i++)
#pragma unroll
        for (int j = 0; j < 4; j++)
#pragma unroll
            for (int k = 0; k < 4; k++) acc[i][j][k] = 0.f;

    auto load_chunk = [&](int chunk) {
        const uint32_t base = sbase + (chunk & 3) * PCHUNK;
        const int k0 = chunk * 64;
#pragma unroll
        for (int i = tid; i < 128 * 8; i += 512) {
            int r = i >> 3, c = i & 7;
            CP16(base + sw128((uint32_t)i * 16),
                 A + (size_t)(rowBase + r) * IND + k0 + c * 8);
        }
#pragma unroll
        for (int i = tid; i < 256 * 8; i += 512) {
            int r = i >> 3, c = i & 7;
            CP16(base + 16384 + sw128((uint32_t)i * 16),
                 W + (size_t)(colBase + r) * IND + k0 + c * 8);
        }
        CP_COMMIT();
    };
    auto compute = [&](uint32_t sA) {
        const uint32_t sB = sA + 16384;
#pragma unroll
        for (int k16 = 0; k16 < 4; k16++) {
            const int aRow = warp_m * 64 + (lane & 15);
            const int aChunk = k16 * 2 + (lane >> 4);
            const int bRow = warp_n * 32 + (lane & 7) + ((lane >> 4) << 3);
            const int bChunk = k16 * 2 + ((lane >> 3) & 1);
            uint32_t af[4][4];
#pragma unroll
            for (int mf = 0; mf < 4; mf++)
                ldsm4(af[mf], sA + sw128((uint32_t)((aRow + mf * 16) * 128 + aChunk * 16)));
            uint32_t bfr[2][4];
            ldsm4(bfr[0], sB + sw128((uint32_t)(bRow * 128 + bChunk * 16)));
            ldsm4(bfr[1], sB + sw128((uint32_t)((bRow + 16) * 128 + bChunk * 16)));
#pragma unroll
            for (int mf = 0; mf < 4; mf++)
#pragma unroll
                for (int nf = 0; nf < 2; nf++) {
                    mma16(acc[mf][nf * 2 + 0], af[mf], &bfr[nf][0]);
                    mma16(acc[mf][nf * 2 + 1], af[mf], &bfr[nf][2]);
                }
        }
    };

    const int nch = IND / 64;    // 196
    load_chunk(0);
    load_chunk(1);
    load_chunk(2);

#pragma unroll 1
    for (int c = 0; c < nch; ++c) {
        asm volatile("cp.async.wait_group 2;" ::: "memory");
        __syncthreads();
        compute(sbase + (c & 3) * PCHUNK);
        if (c + 3 < nch) load_chunk(c + 3);
        else CP_COMMIT();
    }

    // ---- epilogue (packed 32-bit stores for K/Q) ----
#pragma unroll
    for (int mf = 0; mf < 4; mf++) {
#pragma unroll
        for (int nf = 0; nf < 4; nf++) {
            const int r0 = rowBase + warp_m * 64 + mf * 16 + (lane >> 2);
            const int c0 = colBase + warp_n * 32 + nf * 8 + (lane & 3) * 2;
#pragma unroll
            for (int half = 0; half < 2; half++) {
                const int rr = r0 + half * 8;
                const float v0 = acc[mf][nf][half * 2 + 0] + bias[c0];
                const float v1 = acc[mf][nf][half * 2 + 1] + bias[c0 + 1];
                if (task == 0) {
                    *(uint32_t*)(g_Kh + (size_t)rr * APP_MDIM + c0) =
                        pack2h(__float2half_rn(v0), __float2half_rn(v1));
                } else if (task == 1) {
                    *(uint32_t*)(g_Qh + (size_t)rr * APP_MDIM + c0) =
                        pack2h(__float2half_rn(v0), __float2half_rn(v1));
                } else {
#pragma unroll
                    for (int e = 0; e < 2; e++) {
                        const int cc = c0 + e;
                        const int b = rr >> 10, n = rr & 1023;
                        const int hh = cc >> 6, v = cc & 63;
                        g_Vth[(((size_t)(b * HEADS + hh)) * DVV + v) * NN_ + n] =
                            __float2half_rn(e ? v1 : v0);
                    }
                }
            }
        }
    }
}

// ============================================================================
// Fused attention (fp16): Q fragments in registers, poly-exp softmax, 1-pass PV.
// ============================================================================
#define ATT_NC      64
#define ATT_CHUNKS  (NN_ / ATT_NC)      // 16
#define ATT_QBYTES  65536
#define ATT_KBYTES  32768
#define ATT_STAGE   40960               // K + V
#define ATT_SNORM   (ATT_QBYTES + 4 * ATT_STAGE)   // 229376
#define ATT_SMEM    (ATT_SNORM + 512)              // 229888

__global__ void __launch_bounds__(256, 1) attn_fused_kernel(float* __restrict__ out)
{
    extern __shared__ char sm[];
    const uint32_t sbase = smem_u32(sm);
    const int tid = threadIdx.x, wid = tid >> 5, lane = tid & 31;
    const int z = blockIdx.y, b = z >> 2, h = z & 3;
    const int mbase = blockIdx.x * 128;

    const h16* Qg = g_Qh + ((size_t)(b * 1024 + mbase)) * 1024 + h * 256;
    const h16* Kg = g_Kh + ((size_t)(b * 1024)) * 1024 + h * 256;
    const h16* Vhg = g_Vth + (size_t)z * DVV * NN_;

#pragma unroll
    for (int j = 0; j < 16; j++) {
        int i = tid + j * 256;
        int ks = i >> 10, r = (i >> 3) & 127, c = i & 7;
        CP16(sbase + ks * 16384 + sw128((uint32_t)(r * 128 + c * 16)),
             Qg + (size_t)r * 1024 + ks * 64 + c * 8);
    }
    CP_COMMIT();

    auto load_kv = [&](int it) {
        const uint32_t st = sbase + ATT_QBYTES + (it & 3) * ATT_STAGE;
        const int n0 = it * ATT_NC;
#pragma unroll
        for (int j = 0; j < 8; j++) {
            int i = tid + j * 256;
            int ks = i >> 9, r = (i >> 3) & 63, c = i & 7;
            CP16(st + ks * 8192 + sw128((uint32_t)(r * 128 + c * 16)),
                 Kg + (size_t)(n0 + r) * 1024 + ks * 64 + c * 8);
        }
#pragma unroll
        for (int j = 0; j < 2; j++) {
            int i = tid + j * 256;
            int r = i >> 3, c = i & 7;
            CP16(st + ATT_KBYTES + sw128((uint32_t)(r * 128 + c * 16)),
                 Vhg + (size_t)r * NN_ + n0 + c * 8);
        }
        CP_COMMIT();
    };
    load_kv(0);
    load_kv(1);
    load_kv(2);

    asm volatile("cp.async.wait_group 3;" ::: "memory");   // Q landed
    __syncthreads();

    if (tid < 128) {
        float ss = 0.f;
#pragma unroll
        for (int ks = 0; ks < 4; ks++)
#pragma unroll
            for (int c = 0; c < 8; c++) {
                uint4 v = *(uint4*)(sm + ks * 16384 + sw128((uint32_t)(tid * 128 + c * 16)));
                uint32_t ww[4] = {v.x, v.y, v.z, v.w};
#pragma unroll
                for (int e = 0; e < 4; e++) {
                    float lo = __half2float(__ushort_as_half((uint16_t)(ww[e] & 0xffff)));
                    float hi = __half2float(__ushort_as_half((uint16_t)(ww[e] >> 16)));
                    ss += lo * lo + hi * hi;
                }
            }
        *(float*)(sm + ATT_SNORM + tid * 4) = rsqrtf(ss) * (1.0f / 256.0f);
    }
    __syncthreads();

    const int rw = wid * 16 + (lane >> 2);
    const float sc0 = *(const float*)(sm + ATT_SNORM + rw * 4);
    const float sc1 = *(const float*)(sm + ATT_SNORM + (rw + 8) * 4);

    const int aRow = wid * 16 + (lane & 15);
    const int bRowBase = (lane & 7) + ((lane >> 4) << 3);
    uint32_t qf[4][4][4];
#pragma unroll
    for (int ks = 0; ks < 4; ks++)
#pragma unroll
        for (int k16 = 0; k16 < 4; k16++) {
            const int aChunk = k16 * 2 + (lane >> 4);
            ldsm4(qf[ks][k16],
                  sbase + ks * 16384 + sw128((uint32_t)(aRow * 128 + aChunk * 16)));
        }

    float acc_o[8][4];
#pragma unroll
    for (int j = 0; j < 8; j++)
#pragma unroll
        for (int e = 0; e < 4; e++) acc_o[j][e] = 0.f;
    float ps0a = 0.f, ps0b = 0.f, ps1a = 0.f, ps1b = 0.f;

#pragma unroll 1
    for (int it = 0; it < ATT_CHUNKS; ++it) {
        asm volatile("cp.async.wait_group 2;" ::: "memory");
        __syncthreads();
        const uint32_t st = sbase + ATT_QBYTES + (it & 3) * ATT_STAGE;

        float acc_s[8][4];
#pragma unroll
        for (int t = 0; t < 8; t++)
#pragma unroll
            for (int e = 0; e < 4; e++) acc_s[t][e] = 0.f;

#pragma unroll
        for (int ks = 0; ks < 4; ks++) {
#pragma unroll
            for (int k16 = 0; k16 < 4; k16++) {
                const int bChunk = k16 * 2 + ((lane >> 3) & 1);
#pragma unroll
                for (int p = 0; p < 4; p++) {
                    uint32_t bfr[4];
                    ldsm4(bfr, st + ks * 8192 +
                               sw128((uint32_t)((p * 16 + bRowBase) * 128 + bChunk * 16)));
                    mma16(acc_s[p * 2 + 0], qf[ks][k16], &bfr[0]);
                    mma16(acc_s[p * 2 + 1], qf[ks][k16], &bfr[2]);
                }
            }
        }

        uint32_t pph[8][2];
#pragma unroll
        for (int t = 0; t < 8; t++) {
            float p0 = exp_poly(acc_s[t][0] * sc0);
            float p1 = exp_poly(acc_s[t][1] * sc0);
            float p2 = exp_poly(acc_s[t][2] * sc1);
            float p3 = exp_poly(acc_s[t][3] * sc1);
            if (t & 1) { ps0b += p0 + p1; ps1b += p2 + p3; }
            else       { ps0a += p0 + p1; ps1a += p2 + p3; }
            pph[t][0] = pack2h(__float2half_rn(p0), __float2half_rn(p1));
            pph[t][1] = pack2h(__float2half_rn(p2), __float2half_rn(p3));
        }

        const uint32_t vh = st + ATT_KBYTES;
#pragma unroll
        for (int kk = 0; kk < 4; kk++) {
            uint32_t Ahf[4] = {pph[2 * kk][0], pph[2 * kk][1],
                               pph[2 * kk + 1][0], pph[2 * kk + 1][1]};
            const int bChunk = kk * 2 + ((lane >> 3) & 1);
#pragma unroll
            for (int p = 0; p < 4; p++) {
                uint32_t bh[4];
                ldsm4(bh, vh + sw128((uint32_t)((p * 16 + bRowBase) * 128 + bChunk * 16)));
                mma16(acc_o[p * 2 + 0], Ahf, &bh[0]);
                mma16(acc_o[p * 2 + 1], Ahf, &bh[2]);
            }
        }

        if (it + 3 < ATT_CHUNKS) load_kv(it + 3);
        else CP_COMMIT();
    }

    float psum0 = ps0a + ps0b, psum1 = ps1a + ps1b;
    psum0 += __shfl_xor_sync(0xffffffffu, psum0, 1);
    psum0 += __shfl_xor_sync(0xffffffffu, psum0, 2);
    psum1 += __shfl_xor_sync(0xffffffffu, psum1, 1);
    psum1 += __shfl_xor_sync(0xffffffffu, psum1, 2);
    const float inv0 = 1.0f / psum0, inv1 = 1.0f / psum1;

    const int m0 = mbase + rw;
#pragma unroll
    for (int j = 0; j < 8; j++) {
        const int col = h * 64 + j * 8 + (lane & 3) * 2;
        float2 o0 = make_float2(acc_o[j][0] * inv0, acc_o[j][1] * inv0);
        float2 o1 = make_float2(acc_o[j][2] * inv1, acc_o[j][3] * inv1);
        *(float2*)(out + ((size_t)(b * 1024 + m0)) * 256 + col) = o0;
        *(float2*)(out + ((size_t)(b * 1024 + m0 + 8)) * 256 + col) = o1;
    }
}

// ============================================================================
// Merged prep kernel: convert (both tensors) + weight transpose, 1D dispatch.
// bid < NCONV: convert (thread -> one uint4 = 8 floats).
// else: wsplit tile decode (K: 32x392, Q: 32x392, V: 8x392 tiles of 32x32).
// ============================================================================
#define N8_PER   ((BB * NN_ * IND) / 8)           // 12,845,056
#define NCONV    ((2 * N8_PER) / 256)             // 100,352 CTAs
#define WT_KQ    (32 * (IND / 32))                // 12,544 tiles
#define WT_V     (8 * (IND / 32))                 // 3,136 tiles
#define NPREP    (NCONV + 2 * WT_KQ + WT_V)       // 128,576

__global__ void __launch_bounds__(256) prep_kernel(
    const float4* __restrict__ A1, const float4* __restrict__ A2,
    const float* __restrict__ Wk, const float* __restrict__ Wq,
    const float* __restrict__ Wv)
{
    const int bid = blockIdx.x;
    if (bid < NCONV) {
        // ---- convert ----
        int i = bid * 256 + threadIdx.x;
        const float4* src;
        uint4* dst;
        int j;
        if (i < N8_PER) { src = A1; dst = reinterpret_cast<uint4*>(g_A1h); j = i; }
        else            { src = A2; dst = reinterpret_cast<uint4*>(g_A2h); j = i - N8_PER; }
        float4 a = src[2 * j], b = src[2 * j + 1];
        dst[j] = make_uint4(
            pack2h(__float2half_rn(a.x), __float2half_rn(a.y)),
            pack2h(__float2half_rn(a.z), __float2half_rn(a.w)),
            pack2h(__float2half_rn(b.x), __float2half_rn(b.y)),
            pack2h(__float2half_rn(b.z), __float2half_rn(b.w)));
        return;
    }
    // ---- weight transpose ----
    int t = bid - NCONV;
    const float* W;
    h16* Th;
    int Nc, xt;
    if (t < WT_KQ)               { W = Wk; Th = g_Wkh; Nc = APP_MDIM; xt = t; }
    else if (t < 2 * WT_KQ)      { W = Wq; Th = g_Wqh; Nc = APP_MDIM; xt = t - WT_KQ; }
    else                         { W = Wv; Th = g_Wvh; Nc = APP_DIM;  xt = t - 2 * WT_KQ; }
    const int xtiles = Nc / 32;
    const int n0 = (xt % xtiles) * 32;
    const int k0 = (xt / xtiles) * 32;

    __shared__ float ts[32][33];
    int tx = threadIdx.x & 31, ty = threadIdx.x >> 5;
#pragma unroll
    for (int i = 0; i < 4; i++)
        ts[ty + i * 8][tx] = W[(size_t)(k0 + ty + i * 8) * Nc + n0 + tx];
    __syncthreads();
#pragma unroll
    for (int i = 0; i < 4; i++) {
        int n = n0 + ty + i * 8, k = k0 + tx;
        Th[(size_t)n * IND + k] = __float2half_rn(ts[tx][ty + i * 8]);
    }
}

// ============================================================================
// Launch — serial, 3 kernels
// ============================================================================
extern "C" void kernel_launch(void* const* d_in, const int* in_sizes, int n_in,
                              void* d_out, int out_size)
{
    const float* first_app  = (const float*)d_in[0];
    const float* second_app = (const float*)d_in[1];
    const float* Wk = (const float*)d_in[2];
    const float* bk = (const float*)d_in[3];
    const float* Wq = (const float*)d_in[4];
    const float* bq = (const float*)d_in[5];
    const float* Wv = (const float*)d_in[6];
    const float* bv = (const float*)d_in[7];
    float* out = (float*)d_out;

    cudaFuncSetAttribute(proj_all_kernel, cudaFuncAttributeMaxDynamicSharedMemorySize, SM_PROJ);
    cudaFuncSetAttribute(attn_fused_kernel, cudaFuncAttributeMaxDynamicSharedMemorySize, ATT_SMEM);

    // 1) prep: convert activations + transpose weights (single launch)
    prep_kernel<<<NPREP, 256>>>(
        (const float4*)first_app, (const float4*)second_app, Wk, Wq, Wv);

    // 2) all projections: K (x=0..3), Q (x=4..7), V (x=8)
    proj_all_kernel<<<dim3(9, (BB * NN_) / 128), 512, SM_PROJ>>>(bk, bq, bv);

    // 3) fused attention
    attn_fused_kernel<<<dim3(MM_ / 128, BB * HEADS), 256, ATT_SMEM>>>(out);
}